// round 5
// baseline (speedup 1.0000x reference)
#include <cuda_runtime.h>
#include <cuda_bf16.h>
#include <cstdint>

// Shapes (fixed): B=4, LK=256, NQ=64, H=8, DK=DV=64, DM=512
#define B_ 4
#define LK_ 256
#define NQ_ 64
#define H_ 8
#define DM_ 512

// ---------------- scratch (device globals; no allocation) ----------------
__device__ float g_PQ[B_ * LK_ * DM_];
__device__ float g_PK[B_ * LK_ * DM_];
__device__ float g_PV[B_ * LK_ * DM_];
__device__ float g_PU[B_ * NQ_ * DM_];
__device__ float g_OUT[B_ * LK_ * DM_];
__device__ float g_A[B_ * LK_ * DM_];
__device__ float g_QT[B_ * LK_ * NQ_ * H_];
__device__ float g_VF[H_ * B_ * LK_ * DM_];

// ---------------- tf32 helpers ----------------
__device__ __forceinline__ uint32_t f2tf(float x) {
    uint32_t r;
    asm("cvt.rna.tf32.f32 %0, %1;" : "=r"(r) : "f"(x));
    return r;
}

__device__ __forceinline__ void mma_tf32(
    float& c0, float& c1, float& c2, float& c3,
    uint32_t a0, uint32_t a1, uint32_t a2, uint32_t a3,
    uint32_t b0, uint32_t b1)
{
    asm volatile(
        "mma.sync.aligned.m16n8k8.row.col.f32.tf32.tf32.f32 "
        "{%0,%1,%2,%3},{%4,%5,%6,%7},{%8,%9},{%0,%1,%2,%3};"
        : "+f"(c0), "+f"(c1), "+f"(c2), "+f"(c3)
        : "r"(a0), "r"(a1), "r"(a2), "r"(a3), "r"(b0), "r"(b1));
}

__device__ __forceinline__ void cvt_store(uint32_t* hi, uint32_t* lo, int idx, float4 v) {
    uint32_t h0 = f2tf(v.x), h1 = f2tf(v.y), h2 = f2tf(v.z), h3 = f2tf(v.w);
    uint32_t l0 = f2tf(v.x - __uint_as_float(h0));
    uint32_t l1 = f2tf(v.y - __uint_as_float(h1));
    uint32_t l2 = f2tf(v.z - __uint_as_float(h2));
    uint32_t l3 = f2tf(v.w - __uint_as_float(h3));
    *(uint4*)&hi[idx] = make_uint4(h0, h1, h2, h3);
    *(uint4*)&lo[idx] = make_uint4(l0, l1, l2, l3);
}

// ---------------- core: C(64x64 tile) = X @ W^T, 3xTF32, double-buffered ----------------
// 256 threads = 8 warps (4m x 2n). K multiple of 32.
// Dynamic smem: 2 buffers x 4 arrays x 64*SMS words = 73728 bytes.
#define SMS 36
#define BUFW (4 * 64 * SMS)   // 9216 words per buffer

__device__ __forceinline__ void gemm_core(
    uint32_t* __restrict__ smem,
    const float* __restrict__ X, int ldx,
    const float* __restrict__ W, int ldw,
    float* __restrict__ C, int ldc,
    int K, int m0, int n0)
{
    int tid = threadIdx.x;
    int row0 = tid >> 3, col4 = (tid & 7) * 4;
    const float* Xp = X + (long)(m0 + row0) * ldx + col4;
    const float* Wp = W + (long)(n0 + row0) * ldw + col4;
    const float* Xp2 = Xp + 32 * (long)ldx;
    const float* Wp2 = Wp + 32 * (long)ldw;

    float4 xa = *(const float4*)Xp;
    float4 xb = *(const float4*)Xp2;
    float4 wa = *(const float4*)Wp;
    float4 wb = *(const float4*)Wp2;

    int lane = tid & 31, wrp = tid >> 5;
    int gid = lane >> 2, tig = lane & 3;
    int wm = wrp >> 1, wn = wrp & 1;
    int ra = wm * 16 + gid;

    float acc[4][4];
#pragma unroll
    for (int t = 0; t < 4; ++t)
#pragma unroll
        for (int i = 0; i < 4; ++i) acc[t][i] = 0.f;

    // store chunk 0 into buffer 0
    {
        uint32_t* sAh = smem;
        uint32_t* sAl = smem + 2304;
        uint32_t* sWh = smem + 4608;
        uint32_t* sWl = smem + 6912;
        cvt_store(sAh, sAl, row0 * SMS + col4, xa);
        cvt_store(sAh, sAl, (row0 + 32) * SMS + col4, xb);
        cvt_store(sWh, sWl, row0 * SMS + col4, wa);
        cvt_store(sWh, sWl, (row0 + 32) * SMS + col4, wb);
    }
    __syncthreads();

    int p = 0;
    for (int k0 = 0; k0 < K; k0 += 32) {
        bool more = (k0 + 32 < K);
        if (more) {
            xa = *(const float4*)(Xp + k0 + 32);
            xb = *(const float4*)(Xp2 + k0 + 32);
            wa = *(const float4*)(Wp + k0 + 32);
            wb = *(const float4*)(Wp2 + k0 + 32);
        }
        uint32_t* sAh = smem + p * BUFW;
        uint32_t* sAl = sAh + 2304;
        uint32_t* sWh = sAh + 4608;
        uint32_t* sWl = sAh + 6912;
#pragma unroll
        for (int ks = 0; ks < 4; ++ks) {
            int kk = ks * 8;
            int ia0 = ra * SMS + kk + tig;
            int ia1 = (ra + 8) * SMS + kk + tig;
            uint32_t ah0 = sAh[ia0], ah1 = sAh[ia1];
            uint32_t ah2 = sAh[ia0 + 4], ah3 = sAh[ia1 + 4];
            uint32_t al0 = sAl[ia0], al1 = sAl[ia1];
            uint32_t al2 = sAl[ia0 + 4], al3 = sAl[ia1 + 4];
#pragma unroll
            for (int t = 0; t < 4; ++t) {
                int nn = (wn * 32 + t * 8 + gid) * SMS + kk + tig;
                uint32_t bh0 = sWh[nn], bh1 = sWh[nn + 4];
                uint32_t bl0 = sWl[nn], bl1 = sWl[nn + 4];
                mma_tf32(acc[t][0], acc[t][1], acc[t][2], acc[t][3],
                         ah0, ah1, ah2, ah3, bh0, bh1);
                mma_tf32(acc[t][0], acc[t][1], acc[t][2], acc[t][3],
                         ah0, ah1, ah2, ah3, bl0, bl1);
                mma_tf32(acc[t][0], acc[t][1], acc[t][2], acc[t][3],
                         al0, al1, al2, al3, bh0, bh1);
            }
        }
        if (more) {
            uint32_t* dAh = smem + (p ^ 1) * BUFW;
            uint32_t* dAl = dAh + 2304;
            uint32_t* dWh = dAh + 4608;
            uint32_t* dWl = dAh + 6912;
            cvt_store(dAh, dAl, row0 * SMS + col4, xa);
            cvt_store(dAh, dAl, (row0 + 32) * SMS + col4, xb);
            cvt_store(dWh, dWl, row0 * SMS + col4, wa);
            cvt_store(dWh, dWl, (row0 + 32) * SMS + col4, wb);
            __syncthreads();
        }
        p ^= 1;
    }

#pragma unroll
    for (int t = 0; t < 4; ++t) {
        int cn = n0 + wn * 32 + t * 8 + tig * 2;
        long r1 = (long)(m0 + wm * 16 + gid) * ldc + cn;
        *(float2*)&C[r1] = make_float2(acc[t][0], acc[t][1]);
        *(float2*)&C[r1 + 8 * (long)ldc] = make_float2(acc[t][2], acc[t][3]);
    }
}

// ---------------- fused 4-way projection launch ----------------
__global__ __launch_bounds__(256) void proj4(
    const float* __restrict__ q, const float* __restrict__ k,
    const float* __restrict__ v, const float* __restrict__ qu,
    const float* __restrict__ wq, const float* __restrict__ wk,
    const float* __restrict__ wv, const float* __restrict__ wu,
    float* __restrict__ pq, float* __restrict__ pk,
    float* __restrict__ pv, float* __restrict__ pu)
{
    extern __shared__ uint32_t dsm_p[];
    int z = blockIdx.z;
    const float* X; const float* W; float* C; int M;
    if (z == 0)      { X = q;  W = wq; C = pq; M = B_ * LK_; }
    else if (z == 1) { X = k;  W = wk; C = pk; M = B_ * LK_; }
    else if (z == 2) { X = v;  W = wv; C = pv; M = B_ * LK_; }
    else             { X = qu; W = wu; C = pu; M = B_ * NQ_; }
    int m0 = blockIdx.y * 64;
    if (m0 >= M) return;
    gemm_core(dsm_p, X, DM_, W, DM_, C, DM_, DM_, m0, blockIdx.x * 64);
}

// ---------------- merged A + VF GEMM launch ----------------
// z=0: A = OUT @ fc_w^T (K=512). z=1..8: VF[h] = PV_h @ fc_w_h^T (K=64).
__global__ __launch_bounds__(256) void gemm_avf(
    const float* __restrict__ OUT, const float* __restrict__ PV,
    const float* __restrict__ fcw, float* __restrict__ A,
    float* __restrict__ VF)
{
    extern __shared__ uint32_t dsm_g[];
    int z = blockIdx.z;
    if (z == 0) {
        gemm_core(dsm_g, OUT, DM_, fcw, DM_, A, DM_, DM_,
                  blockIdx.y * 64, blockIdx.x * 64);
    } else {
        int h = z - 1;
        gemm_core(dsm_g, PV + h * 64, DM_, fcw + h * 64, DM_,
                  VF + (long)h * (B_ * LK_ * DM_), DM_, 64,
                  blockIdx.y * 64, blockIdx.x * 64);
    }
}

// ---------------- fused attention: self (x<4) + query probs (x==4) ----------------
__global__ __launch_bounds__(256) void attn_fused(
    const float* __restrict__ PQ, const float* __restrict__ PK,
    const float* __restrict__ PV, const float* __restrict__ PU,
    float* __restrict__ OUT, float* __restrict__ QT)
{
    extern __shared__ float sm[];
    int h = blockIdx.z, b = blockIdx.y;
    int tid = threadIdx.x;
    long kvbase = ((long)b * LK_) * DM_ + h * 64;

    if (blockIdx.x < 4) {
        // ---- self-attention: softmax(QK^T/8) @ V for one 64-row q tile ----
        float* Ks = sm;
        float* Vs = sm + 16384;
        int q0 = blockIdx.x * 64;

        for (int e = tid; e < 16384; e += 256) {
            int j = e >> 6, d = e & 63;
            Ks[e] = PK[kvbase + (long)j * DM_ + d];
            Vs[e] = PV[kvbase + (long)j * DM_ + d];
        }

        int row = tid & 63, qr = tid >> 6;
        float qv[64];
        {
            const float* qp = PQ + kvbase + (long)(q0 + row) * DM_;
#pragma unroll
            for (int d = 0; d < 64; d += 4) {
                float4 t = *(const float4*)(qp + d);
                qv[d] = t.x; qv[d + 1] = t.y; qv[d + 2] = t.z; qv[d + 3] = t.w;
            }
        }
        __syncthreads();

        float m = -1e30f, l = 0.f;
        float accv[64];
#pragma unroll
        for (int d = 0; d < 64; ++d) accv[d] = 0.f;

        int jbase = qr * 64;
        for (int jc = 0; jc < 64; jc += 8) {
            float s[8];
#pragma unroll
            for (int jj = 0; jj < 8; ++jj) {
                const float* kp = Ks + (jbase + jc + jj) * 64;
                float a = 0.f;
#pragma unroll
                for (int d = 0; d < 64; d += 4) {
                    float4 k4 = *(const float4*)(kp + d);
                    a += qv[d] * k4.x + qv[d + 1] * k4.y + qv[d + 2] * k4.z + qv[d + 3] * k4.w;
                }
                s[jj] = a * 0.125f;
            }
            float cm = s[0];
#pragma unroll
            for (int jj = 1; jj < 8; ++jj) cm = fmaxf(cm, s[jj]);
            float nm = fmaxf(m, cm);
            float r = __expf(m - nm);
            l *= r;
#pragma unroll
            for (int d = 0; d < 64; ++d) accv[d] *= r;
            m = nm;
#pragma unroll
            for (int jj = 0; jj < 8; ++jj) {
                float p = __expf(s[jj] - m);
                l += p;
                const float* vp = Vs + (jbase + jc + jj) * 64;
#pragma unroll
                for (int d = 0; d < 64; d += 4) {
                    float4 v4 = *(const float4*)(vp + d);
                    accv[d] += p * v4.x; accv[d + 1] += p * v4.y;
                    accv[d + 2] += p * v4.z; accv[d + 3] += p * v4.w;
                }
            }
        }
        __syncthreads();  // Ks/Vs dead; reuse

        float* mbuf = Vs;
        float* lbuf = Vs + 256;
        mbuf[row * 4 + qr] = m;
        __syncthreads();
        float M = fmaxf(fmaxf(mbuf[row * 4 + 0], mbuf[row * 4 + 1]),
                        fmaxf(mbuf[row * 4 + 2], mbuf[row * 4 + 3]));
        float f = __expf(m - M);
        lbuf[row * 4 + qr] = l * f;
        float* obuf = Ks + (qr * 64 + row) * 64;
#pragma unroll
        for (int d = 0; d < 64; ++d) obuf[d] = accv[d] * f;
        __syncthreads();
        float L = lbuf[row * 4 + 0] + lbuf[row * 4 + 1] + lbuf[row * 4 + 2] + lbuf[row * 4 + 3];
        float invL = 1.f / L;

        float* op = OUT + kvbase + (long)(q0 + row) * DM_;
#pragma unroll
        for (int dd = 0; dd < 16; dd += 4) {
            int d = qr * 16 + dd;
            float4 t0 = *(const float4*)&Ks[(0 * 64 + row) * 64 + d];
            float4 t1 = *(const float4*)&Ks[(1 * 64 + row) * 64 + d];
            float4 t2 = *(const float4*)&Ks[(2 * 64 + row) * 64 + d];
            float4 t3 = *(const float4*)&Ks[(3 * 64 + row) * 64 + d];
            float4 o;
            o.x = (t0.x + t1.x + t2.x + t3.x) * invL;
            o.y = (t0.y + t1.y + t2.y + t3.y) * invL;
            o.z = (t0.z + t1.z + t2.z + t3.z) * invL;
            o.w = (t0.w + t1.w + t2.w + t3.w) * invL;
            *(float4*)(op + d) = o;
        }
    } else {
        // ---- query attention probs: softmax(QU K^T / 8), scores in registers ----
        float* Ks = sm;
        float* red = sm + 16384;   // 1024 floats

        for (int e = tid; e < 16384; e += 256) {
            int j = e >> 6, d = e & 63;
            Ks[e] = PK[kvbase + (long)j * DM_ + d];
        }

        int n = tid >> 2, qr = tid & 3;
        float qv[64];
        {
            const float* qp = PU + ((long)(b * NQ_ + n)) * DM_ + h * 64;
#pragma unroll
            for (int d = 0; d < 64; d += 4) {
                float4 t = *(const float4*)(qp + d);
                qv[d] = t.x; qv[d + 1] = t.y; qv[d + 2] = t.z; qv[d + 3] = t.w;
            }
        }
        __syncthreads();

        float s[64];
        float lm = -1e30f;
#pragma unroll 4
        for (int kk = 0; kk < 64; ++kk) {
            const float* kp = Ks + (qr * 64 + kk) * 64;
            float a = 0.f;
#pragma unroll
            for (int d = 0; d < 64; d += 4) {
                float4 k4 = *(const float4*)(kp + d);
                a += qv[d] * k4.x + qv[d + 1] * k4.y + qv[d + 2] * k4.z + qv[d + 3] * k4.w;
            }
            s[kk] = a * 0.125f;
            lm = fmaxf(lm, s[kk]);
        }
        red[n * 4 + qr] = lm;
        __syncthreads();
        float M = fmaxf(fmaxf(red[n * 4 + 0], red[n * 4 + 1]),
                        fmaxf(red[n * 4 + 2], red[n * 4 + 3]));
        float es = 0.f;
#pragma unroll
        for (int kk = 0; kk < 64; ++kk) {
            float e = __expf(s[kk] - M);
            s[kk] = e;
            es += e;
        }
        red[512 + n * 4 + qr] = es;
        __syncthreads();
        float S = red[512 + n * 4 + 0] + red[512 + n * 4 + 1] +
                  red[512 + n * 4 + 2] + red[512 + n * 4 + 3];
        float inv = 1.f / S;
#pragma unroll 4
        for (int kk = 0; kk < 64; ++kk) {
            int k = qr * 64 + kk;
            QT[((long)(b * LK_ + k) * NQ_ + n) * 8 + h] = s[kk] * inv;
        }
    }
}

// ---------------- combine + residual + LayerNorm (analytic stats, sync-free stream) ----------------
__global__ __launch_bounds__(256) void combine_ln(
    const float* __restrict__ VF, const float* __restrict__ A,
    const float* __restrict__ QT, const float* __restrict__ qin,
    const float* __restrict__ fc_b, const float* __restrict__ ln_w,
    const float* __restrict__ ln_b, float* __restrict__ out)
{
    __shared__ float qt[512];
    __shared__ float red[54 * 8];
    __shared__ float S[54];
    __shared__ float musm[64], rsm[64];

    int k = blockIdx.x, b = blockIdx.y;
    long rk = (long)b * LK_ + k;
    int tid = threadIdx.x, lane = tid & 31, wid = tid >> 5;

    float2 vf[8];
#pragma unroll
    for (int h = 0; h < 8; ++h)
        vf[h] = ((const float2*)(VF + (long)h * (B_ * LK_ * DM_) + rk * DM_))[tid];
    float2 bb = ((const float2*)(A + rk * DM_))[tid];
    float2 qv = ((const float2*)(qin + rk * DM_))[tid];
    float2 fb = ((const float2*)fc_b)[tid];
    bb.x += qv.x + fb.x; bb.y += qv.y + fb.y;
    float2 lwv = ((const float2*)ln_w)[tid];
    float2 lbv = ((const float2*)ln_b)[tid];
    for (int e = tid; e < 512; e += 256) qt[e] = QT[rk * 512 + e];

    // 54 reduction scalars: sum(b), sum(vf_h), b.b, b.vf_h, Gram vf_h.vf_h'
    float part[54];
    part[0] = bb.x + bb.y;
#pragma unroll
    for (int h = 0; h < 8; ++h) part[1 + h] = vf[h].x + vf[h].y;
    part[9] = bb.x * bb.x + bb.y * bb.y;
#pragma unroll
    for (int h = 0; h < 8; ++h) part[10 + h] = bb.x * vf[h].x + bb.y * vf[h].y;
    {
        int c = 18;
#pragma unroll
        for (int h = 0; h < 8; ++h)
#pragma unroll
            for (int h2 = h; h2 < 8; ++h2)
                part[c++] = vf[h].x * vf[h2].x + vf[h].y * vf[h2].y;
    }
#pragma unroll
    for (int i = 0; i < 54; ++i) {
#pragma unroll
        for (int o = 16; o; o >>= 1)
            part[i] += __shfl_down_sync(0xffffffffu, part[i], o);
    }
    if (lane == 0) {
#pragma unroll
        for (int i = 0; i < 54; ++i) red[i * 8 + wid] = part[i];
    }
    __syncthreads();
    if (tid < 54) {
        float s = 0.f;
#pragma unroll
        for (int w = 0; w < 8; ++w) s += red[tid * 8 + w];
        S[tid] = s;
    }
    __syncthreads();
    // per-n stats from quadratic form (threads 0..63)
    if (tid < 64) {
        float g[8];
#pragma unroll
        for (int h = 0; h < 8; ++h) g[h] = qt[tid * 8 + h];
        float sum = S[0];
        float sq = S[9];
#pragma unroll
        for (int h = 0; h < 8; ++h) {
            sum += g[h] * S[1 + h];
            sq += 2.f * g[h] * S[10 + h];
        }
        int c = 18;
#pragma unroll
        for (int h = 0; h < 8; ++h)
#pragma unroll
            for (int h2 = h; h2 < 8; ++h2) {
                float co = (h == h2) ? g[h] * g[h] : 2.f * g[h] * g[h2];
                sq += co * S[c++];
            }
        float mu = sum * (1.f / 512.f);
        float var = sq * (1.f / 512.f) - mu * mu;
        musm[tid] = mu;
        rsm[tid] = rsqrtf(var + 1e-5f);
    }
    __syncthreads();

    // sync-free streaming epilogue
    long obase = (long)b * (NQ_ * LK_ * DM_) + (long)k * DM_;
    for (int n = 0; n < NQ_; ++n) {
        float2 t = bb;
#pragma unroll
        for (int h = 0; h < 8; ++h) {
            float g = qt[n * 8 + h];
            t.x += g * vf[h].x;
            t.y += g * vf[h].y;
        }
        float mu = musm[n], rstd = rsm[n];
        float2 o2;
        o2.x = (t.x - mu) * rstd * lwv.x + lbv.x;
        o2.y = (t.y - mu) * rstd * lwv.y + lbv.y;
        ((float2*)(out + obase + (long)n * (LK_ * DM_)))[tid] = o2;
    }
}

// ---------------- host launcher ----------------
extern "C" void kernel_launch(void* const* d_in, const int* in_sizes, int n_in,
                              void* d_out, int out_size)
{
    (void)in_sizes; (void)n_in; (void)out_size;
    const float* q     = (const float*)d_in[0];
    const float* k     = (const float*)d_in[1];
    const float* v     = (const float*)d_in[2];
    const float* query = (const float*)d_in[3];
    const float* w_qs  = (const float*)d_in[4];
    const float* w_ks  = (const float*)d_in[5];
    const float* w_vs  = (const float*)d_in[6];
    const float* w_qu  = (const float*)d_in[7];
    const float* fc_w  = (const float*)d_in[8];
    const float* fc_b  = (const float*)d_in[9];
    const float* ln_w  = (const float*)d_in[10];
    const float* ln_b  = (const float*)d_in[11];
    float* out = (float*)d_out;

    float *pPQ, *pPK, *pPV, *pPU, *pOUT, *pA, *pQT, *pVF;
    cudaGetSymbolAddress((void**)&pPQ,  g_PQ);
    cudaGetSymbolAddress((void**)&pPK,  g_PK);
    cudaGetSymbolAddress((void**)&pPV,  g_PV);
    cudaGetSymbolAddress((void**)&pPU,  g_PU);
    cudaGetSymbolAddress((void**)&pOUT, g_OUT);
    cudaGetSymbolAddress((void**)&pA,   g_A);
    cudaGetSymbolAddress((void**)&pQT,  g_QT);
    cudaGetSymbolAddress((void**)&pVF,  g_VF);

    const int GEMM_SMEM = 2 * BUFW * 4;   // 73728 B
    const int ATTN_SMEM = 2 * 16384 * 4;  // 131072 B
    cudaFuncSetAttribute(proj4,      cudaFuncAttributeMaxDynamicSharedMemorySize, GEMM_SMEM);
    cudaFuncSetAttribute(gemm_avf,   cudaFuncAttributeMaxDynamicSharedMemorySize, GEMM_SMEM);
    cudaFuncSetAttribute(attn_fused, cudaFuncAttributeMaxDynamicSharedMemorySize, ATTN_SMEM);

    dim3 thr(256);

    // All four projections in one launch (tf32 tensor path)
    proj4<<<dim3(8, 16, 4), thr, GEMM_SMEM>>>(q, k, v, query, w_qs, w_ks, w_vs, w_qu,
                                              pPQ, pPK, pPV, pPU);

    // Self-attention + query attention probs in one launch
    attn_fused<<<dim3(5, B_, H_), thr, ATTN_SMEM>>>(pPQ, pPK, pPV, pPU, pOUT, pQT);

    // A = OUT @ fc_w^T  and  VF[h] = PV_h @ fc_w_h^T  in one launch
    gemm_avf<<<dim3(8, 16, 9), thr, GEMM_SMEM>>>(pOUT, pPV, fc_w, pA, pVF);

    // Combine + residual + LayerNorm -> output
    combine_ln<<<dim3(LK_, B_), thr>>>(pVF, pA, pQT, q, fc_b, ln_w, ln_b, out);
}

// round 7
// speedup vs baseline: 1.5324x; 1.5324x over previous
#include <cuda_runtime.h>
#include <cuda_bf16.h>
#include <cstdint>

// Shapes (fixed): B=4, LK=256, NQ=64, H=8, DK=DV=64, DM=512
#define B_ 4
#define LK_ 256
#define NQ_ 64
#define H_ 8
#define DM_ 512

// ---------------- scratch (device globals; no allocation) ----------------
__device__ float g_PQ[B_ * LK_ * DM_];
__device__ float g_PK[B_ * LK_ * DM_];
__device__ float g_PV[B_ * LK_ * DM_];
__device__ float g_PU[B_ * NQ_ * DM_];
__device__ float g_OUT[B_ * LK_ * DM_];
__device__ float g_A[B_ * LK_ * DM_];
__device__ float g_QT[B_ * LK_ * NQ_ * H_];
__device__ float g_VF[H_ * B_ * LK_ * DM_];

// ---------------- tf32 helpers ----------------
__device__ __forceinline__ uint32_t f2tf(float x) {
    uint32_t r;
    asm("cvt.rna.tf32.f32 %0, %1;" : "=r"(r) : "f"(x));
    return r;
}

__device__ __forceinline__ void mma_tf32(
    float& c0, float& c1, float& c2, float& c3,
    uint32_t a0, uint32_t a1, uint32_t a2, uint32_t a3,
    uint32_t b0, uint32_t b1)
{
    asm volatile(
        "mma.sync.aligned.m16n8k8.row.col.f32.tf32.tf32.f32 "
        "{%0,%1,%2,%3},{%4,%5,%6,%7},{%8,%9},{%0,%1,%2,%3};"
        : "+f"(c0), "+f"(c1), "+f"(c2), "+f"(c3)
        : "r"(a0), "r"(a1), "r"(a2), "r"(a3), "r"(b0), "r"(b1));
}

__device__ __forceinline__ void cvt_store(uint32_t* hi, uint32_t* lo, int idx, float4 v) {
    uint32_t h0 = f2tf(v.x), h1 = f2tf(v.y), h2 = f2tf(v.z), h3 = f2tf(v.w);
    uint32_t l0 = f2tf(v.x - __uint_as_float(h0));
    uint32_t l1 = f2tf(v.y - __uint_as_float(h1));
    uint32_t l2 = f2tf(v.z - __uint_as_float(h2));
    uint32_t l3 = f2tf(v.w - __uint_as_float(h3));
    *(uint4*)&hi[idx] = make_uint4(h0, h1, h2, h3);
    *(uint4*)&lo[idx] = make_uint4(l0, l1, l2, l3);
}

// ---------------- core: C(64x64 tile) = X @ W^T, 3xTF32 (single-buffer, proven) ----------------
// 256 threads = 8 warps (4m x 2n), warp tile 16x32. K multiple of 32.
#define SMS 36  // smem row stride (words): frag reads conflict-free
__device__ __forceinline__ void gemm_core(
    const float* __restrict__ X, int ldx,
    const float* __restrict__ W, int ldw,
    float* __restrict__ C, int ldc,
    int K, int m0, int n0)
{
    __shared__ uint32_t sAh[64 * SMS], sAl[64 * SMS];
    __shared__ uint32_t sWh[64 * SMS], sWl[64 * SMS];

    int tid = threadIdx.x;
    int row0 = tid >> 3, col4 = (tid & 7) * 4;
    const float* Xp = X + (long)(m0 + row0) * ldx + col4;
    const float* Wp = W + (long)(n0 + row0) * ldw + col4;
    const float* Xp2 = Xp + 32 * (long)ldx;
    const float* Wp2 = Wp + 32 * (long)ldw;

    float4 xa = *(const float4*)Xp;
    float4 xb = *(const float4*)Xp2;
    float4 wa = *(const float4*)Wp;
    float4 wb = *(const float4*)Wp2;

    int lane = tid & 31, wrp = tid >> 5;
    int gid = lane >> 2, tig = lane & 3;
    int wm = wrp >> 1, wn = wrp & 1;
    int ra = wm * 16 + gid;

    float acc[4][4];
#pragma unroll
    for (int t = 0; t < 4; ++t)
#pragma unroll
        for (int i = 0; i < 4; ++i) acc[t][i] = 0.f;

    for (int k0 = 0; k0 < K; k0 += 32) {
        cvt_store(sAh, sAl, row0 * SMS + col4, xa);
        cvt_store(sAh, sAl, (row0 + 32) * SMS + col4, xb);
        cvt_store(sWh, sWl, row0 * SMS + col4, wa);
        cvt_store(sWh, sWl, (row0 + 32) * SMS + col4, wb);
        __syncthreads();
        if (k0 + 32 < K) {
            xa = *(const float4*)(Xp + k0 + 32);
            xb = *(const float4*)(Xp2 + k0 + 32);
            wa = *(const float4*)(Wp + k0 + 32);
            wb = *(const float4*)(Wp2 + k0 + 32);
        }
#pragma unroll
        for (int ks = 0; ks < 4; ++ks) {
            int kk = ks * 8;
            int ia0 = ra * SMS + kk + tig;
            int ia1 = (ra + 8) * SMS + kk + tig;
            uint32_t ah0 = sAh[ia0], ah1 = sAh[ia1];
            uint32_t ah2 = sAh[ia0 + 4], ah3 = sAh[ia1 + 4];
            uint32_t al0 = sAl[ia0], al1 = sAl[ia1];
            uint32_t al2 = sAl[ia0 + 4], al3 = sAl[ia1 + 4];
#pragma unroll
            for (int t = 0; t < 4; ++t) {
                int nn = (wn * 32 + t * 8 + gid) * SMS + kk + tig;
                uint32_t bh0 = sWh[nn], bh1 = sWh[nn + 4];
                uint32_t bl0 = sWl[nn], bl1 = sWl[nn + 4];
                mma_tf32(acc[t][0], acc[t][1], acc[t][2], acc[t][3],
                         ah0, ah1, ah2, ah3, bh0, bh1);
                mma_tf32(acc[t][0], acc[t][1], acc[t][2], acc[t][3],
                         ah0, ah1, ah2, ah3, bl0, bl1);
                mma_tf32(acc[t][0], acc[t][1], acc[t][2], acc[t][3],
                         al0, al1, al2, al3, bh0, bh1);
            }
        }
        __syncthreads();
    }

#pragma unroll
    for (int t = 0; t < 4; ++t) {
        int cn = n0 + wn * 32 + t * 8 + tig * 2;
        long r1 = (long)(m0 + wm * 16 + gid) * ldc + cn;
        *(float2*)&C[r1] = make_float2(acc[t][0], acc[t][1]);
        *(float2*)&C[r1 + 8 * (long)ldc] = make_float2(acc[t][2], acc[t][3]);
    }
}

// ---------------- fused 4-way projection launch ----------------
__global__ __launch_bounds__(256) void proj4(
    const float* __restrict__ q, const float* __restrict__ k,
    const float* __restrict__ v, const float* __restrict__ qu,
    const float* __restrict__ wq, const float* __restrict__ wk,
    const float* __restrict__ wv, const float* __restrict__ wu,
    float* __restrict__ pq, float* __restrict__ pk,
    float* __restrict__ pv, float* __restrict__ pu)
{
    int z = blockIdx.z;
    const float* X; const float* W; float* C; int M;
    if (z == 0)      { X = q;  W = wq; C = pq; M = B_ * LK_; }
    else if (z == 1) { X = k;  W = wk; C = pk; M = B_ * LK_; }
    else if (z == 2) { X = v;  W = wv; C = pv; M = B_ * LK_; }
    else             { X = qu; W = wu; C = pu; M = B_ * NQ_; }
    int m0 = blockIdx.y * 64;
    if (m0 >= M) return;
    gemm_core(X, DM_, W, DM_, C, DM_, DM_, m0, blockIdx.x * 64);
}

// ---------------- merged A + VF GEMM launch ----------------
// z=0: A = OUT @ fc_w^T (K=512). z=1..8: VF[h] = PV_h @ fc_w_h^T (K=64).
__global__ __launch_bounds__(256) void gemm_avf(
    const float* __restrict__ OUT, const float* __restrict__ PV,
    const float* __restrict__ fcw, float* __restrict__ A,
    float* __restrict__ VF)
{
    int z = blockIdx.z;
    if (z == 0) {
        gemm_core(OUT, DM_, fcw, DM_, A, DM_, DM_,
                  blockIdx.y * 64, blockIdx.x * 64);
    } else {
        int h = z - 1;
        gemm_core(PV + h * 64, DM_, fcw + h * 64, DM_,
                  VF + (long)h * (B_ * LK_ * DM_), DM_, 64,
                  blockIdx.y * 64, blockIdx.x * 64);
    }
}

// ---------------- fused self-attention: softmax(QK^T/8) @ V ----------------
__global__ __launch_bounds__(256) void attn_self(
    const float* __restrict__ PQ, const float* __restrict__ PK,
    const float* __restrict__ PV, float* __restrict__ OUT)
{
    extern __shared__ float sm[];
    float* Ks = sm;
    float* Vs = sm + 16384;

    int h = blockIdx.z, b = blockIdx.y, q0 = blockIdx.x * 64;
    int tid = threadIdx.x;
    long kvbase = ((long)b * LK_) * DM_ + h * 64;

    for (int e = tid; e < 16384; e += 256) {
        int j = e >> 6, d = e & 63;
        Ks[e] = PK[kvbase + (long)j * DM_ + d];
        Vs[e] = PV[kvbase + (long)j * DM_ + d];
    }

    int row = tid & 63, qr = tid >> 6;
    float qv[64];
    {
        const float* qp = PQ + kvbase + (long)(q0 + row) * DM_;
#pragma unroll
        for (int d = 0; d < 64; d += 4) {
            float4 t = *(const float4*)(qp + d);
            qv[d] = t.x; qv[d + 1] = t.y; qv[d + 2] = t.z; qv[d + 3] = t.w;
        }
    }
    __syncthreads();

    float m = -1e30f, l = 0.f;
    float accv[64];
#pragma unroll
    for (int d = 0; d < 64; ++d) accv[d] = 0.f;

    int jbase = qr * 64;
    for (int jc = 0; jc < 64; jc += 8) {
        float s[8];
#pragma unroll
        for (int jj = 0; jj < 8; ++jj) {
            const float* kp = Ks + (jbase + jc + jj) * 64;
            float a = 0.f;
#pragma unroll
            for (int d = 0; d < 64; d += 4) {
                float4 k4 = *(const float4*)(kp + d);
                a += qv[d] * k4.x + qv[d + 1] * k4.y + qv[d + 2] * k4.z + qv[d + 3] * k4.w;
            }
            s[jj] = a * 0.125f;
        }
        float cm = s[0];
#pragma unroll
        for (int jj = 1; jj < 8; ++jj) cm = fmaxf(cm, s[jj]);
        float nm = fmaxf(m, cm);
        float r = __expf(m - nm);
        l *= r;
#pragma unroll
        for (int d = 0; d < 64; ++d) accv[d] *= r;
        m = nm;
#pragma unroll
        for (int jj = 0; jj < 8; ++jj) {
            float p = __expf(s[jj] - m);
            l += p;
            const float* vp = Vs + (jbase + jc + jj) * 64;
#pragma unroll
            for (int d = 0; d < 64; d += 4) {
                float4 v4 = *(const float4*)(vp + d);
                accv[d] += p * v4.x; accv[d + 1] += p * v4.y;
                accv[d + 2] += p * v4.z; accv[d + 3] += p * v4.w;
            }
        }
    }
    __syncthreads();  // Ks/Vs dead; reuse for reduction

    float* mbuf = Vs;
    float* lbuf = Vs + 256;
    mbuf[row * 4 + qr] = m;
    __syncthreads();
    float M = fmaxf(fmaxf(mbuf[row * 4 + 0], mbuf[row * 4 + 1]),
                    fmaxf(mbuf[row * 4 + 2], mbuf[row * 4 + 3]));
    float f = __expf(m - M);
    lbuf[row * 4 + qr] = l * f;
    float* obuf = Ks + (qr * 64 + row) * 64;
#pragma unroll
    for (int d = 0; d < 64; ++d) obuf[d] = accv[d] * f;
    __syncthreads();
    float L = lbuf[row * 4 + 0] + lbuf[row * 4 + 1] + lbuf[row * 4 + 2] + lbuf[row * 4 + 3];
    float invL = 1.f / L;

    float* op = OUT + kvbase + (long)(q0 + row) * DM_;
#pragma unroll
    for (int dd = 0; dd < 16; dd += 4) {
        int d = qr * 16 + dd;
        float4 t0 = *(const float4*)&Ks[(0 * 64 + row) * 64 + d];
        float4 t1 = *(const float4*)&Ks[(1 * 64 + row) * 64 + d];
        float4 t2 = *(const float4*)&Ks[(2 * 64 + row) * 64 + d];
        float4 t3 = *(const float4*)&Ks[(3 * 64 + row) * 64 + d];
        float4 o;
        o.x = (t0.x + t1.x + t2.x + t3.x) * invL;
        o.y = (t0.y + t1.y + t2.y + t3.y) * invL;
        o.z = (t0.z + t1.z + t2.z + t3.z) * invL;
        o.w = (t0.w + t1.w + t2.w + t3.w) * invL;
        *(float4*)(op + d) = o;
    }
}

// ---------------- query attention probs: softmax(QU K^T/8), transposed out ----------------
__global__ __launch_bounds__(256) void attn_query(
    const float* __restrict__ PU, const float* __restrict__ PK,
    float* __restrict__ QT)
{
    extern __shared__ float sm[];
    float* Ks = sm;
    float* Ss = sm + 16384;
    float* red = Ss + 64 * 260;

    int b = blockIdx.x, h = blockIdx.y;
    int tid = threadIdx.x;
    long kvbase = ((long)b * LK_) * DM_ + h * 64;

    for (int e = tid; e < 16384; e += 256) {
        int j = e >> 6, d = e & 63;
        Ks[e] = PK[kvbase + (long)j * DM_ + d];
    }

    int n = tid >> 2, qr = tid & 3;
    float qv[64];
    {
        const float* qp = PU + ((long)(b * NQ_ + n)) * DM_ + h * 64;
#pragma unroll
        for (int d = 0; d < 64; d += 4) {
            float4 t = *(const float4*)(qp + d);
            qv[d] = t.x; qv[d + 1] = t.y; qv[d + 2] = t.z; qv[d + 3] = t.w;
        }
    }
    __syncthreads();

    float* srow = Ss + n * 260;
    float lm = -1e30f;
    for (int k = qr * 64; k < qr * 64 + 64; ++k) {
        const float* kp = Ks + k * 64;
        float a = 0.f;
#pragma unroll
        for (int d = 0; d < 64; d += 4) {
            float4 k4 = *(const float4*)(kp + d);
            a += qv[d] * k4.x + qv[d + 1] * k4.y + qv[d + 2] * k4.z + qv[d + 3] * k4.w;
        }
        float sv = a * 0.125f;
        srow[k] = sv;
        lm = fmaxf(lm, sv);
    }
    red[n * 4 + qr] = lm;
    __syncthreads();
    float M = fmaxf(fmaxf(red[n * 4 + 0], red[n * 4 + 1]),
                    fmaxf(red[n * 4 + 2], red[n * 4 + 3]));
    float es = 0.f;
    for (int k = qr * 64; k < qr * 64 + 64; ++k) es += __expf(srow[k] - M);
    red[256 + n * 4 + qr] = es;
    __syncthreads();
    float S = red[256 + n * 4 + 0] + red[256 + n * 4 + 1] +
              red[256 + n * 4 + 2] + red[256 + n * 4 + 3];
    float inv = 1.f / S;
    for (int k = qr * 64; k < qr * 64 + 64; ++k) {
        float p = __expf(srow[k] - M) * inv;
        QT[((long)(b * LK_ + k) * NQ_ + n) * 8 + h] = p;
    }
}

// ---------------- combine + residual + LayerNorm (analytic stats, sync-free stream) ----------------
__global__ __launch_bounds__(256) void combine_ln(
    const float* __restrict__ VF, const float* __restrict__ A,
    const float* __restrict__ QT, const float* __restrict__ qin,
    const float* __restrict__ fc_b, const float* __restrict__ ln_w,
    const float* __restrict__ ln_b, float* __restrict__ out)
{
    __shared__ float qt[512];
    __shared__ float red[54 * 8];
    __shared__ float S[54];
    __shared__ float musm[64], rsm[64];

    int k = blockIdx.x, b = blockIdx.y;
    long rk = (long)b * LK_ + k;
    int tid = threadIdx.x, lane = tid & 31, wid = tid >> 5;

    float2 vf[8];
#pragma unroll
    for (int h = 0; h < 8; ++h)
        vf[h] = ((const float2*)(VF + (long)h * (B_ * LK_ * DM_) + rk * DM_))[tid];
    float2 bb = ((const float2*)(A + rk * DM_))[tid];
    float2 qv = ((const float2*)(qin + rk * DM_))[tid];
    float2 fb = ((const float2*)fc_b)[tid];
    bb.x += qv.x + fb.x; bb.y += qv.y + fb.y;
    float2 lwv = ((const float2*)ln_w)[tid];
    float2 lbv = ((const float2*)ln_b)[tid];
    for (int e = tid; e < 512; e += 256) qt[e] = QT[rk * 512 + e];

    // 54 reduction scalars: sum(b), sum(vf_h), b.b, b.vf_h, Gram vf_h.vf_h'
    float part[54];
    part[0] = bb.x + bb.y;
#pragma unroll
    for (int h = 0; h < 8; ++h) part[1 + h] = vf[h].x + vf[h].y;
    part[9] = bb.x * bb.x + bb.y * bb.y;
#pragma unroll
    for (int h = 0; h < 8; ++h) part[10 + h] = bb.x * vf[h].x + bb.y * vf[h].y;
    {
        int c = 18;
#pragma unroll
        for (int h = 0; h < 8; ++h)
#pragma unroll
            for (int h2 = h; h2 < 8; ++h2)
                part[c++] = vf[h].x * vf[h2].x + vf[h].y * vf[h2].y;
    }
#pragma unroll
    for (int i = 0; i < 54; ++i) {
#pragma unroll
        for (int o = 16; o; o >>= 1)
            part[i] += __shfl_down_sync(0xffffffffu, part[i], o);
    }
    if (lane == 0) {
#pragma unroll
        for (int i = 0; i < 54; ++i) red[i * 8 + wid] = part[i];
    }
    __syncthreads();
    if (tid < 54) {
        float s = 0.f;
#pragma unroll
        for (int w = 0; w < 8; ++w) s += red[tid * 8 + w];
        S[tid] = s;
    }
    __syncthreads();
    // per-n stats from quadratic form (threads 0..63)
    if (tid < 64) {
        float g[8];
#pragma unroll
        for (int h = 0; h < 8; ++h) g[h] = qt[tid * 8 + h];
        float sum = S[0];
        float sq = S[9];
#pragma unroll
        for (int h = 0; h < 8; ++h) {
            sum += g[h] * S[1 + h];
            sq += 2.f * g[h] * S[10 + h];
        }
        int c = 18;
#pragma unroll
        for (int h = 0; h < 8; ++h)
#pragma unroll
            for (int h2 = h; h2 < 8; ++h2) {
                float co = (h == h2) ? g[h] * g[h] : 2.f * g[h] * g[h2];
                sq += co * S[c++];
            }
        float mu = sum * (1.f / 512.f);
        float var = sq * (1.f / 512.f) - mu * mu;
        musm[tid] = mu;
        rsm[tid] = rsqrtf(var + 1e-5f);
    }
    __syncthreads();

    // sync-free streaming epilogue
    long obase = (long)b * (NQ_ * LK_ * DM_) + (long)k * DM_;
    for (int n = 0; n < NQ_; ++n) {
        float2 t = bb;
#pragma unroll
        for (int h = 0; h < 8; ++h) {
            float g = qt[n * 8 + h];
            t.x += g * vf[h].x;
            t.y += g * vf[h].y;
        }
        float mu = musm[n], rstd = rsm[n];
        float2 o2;
        o2.x = (t.x - mu) * rstd * lwv.x + lbv.x;
        o2.y = (t.y - mu) * rstd * lwv.y + lbv.y;
        ((float2*)(out + obase + (long)n * (LK_ * DM_)))[tid] = o2;
    }
}

// ---------------- host launcher ----------------
extern "C" void kernel_launch(void* const* d_in, const int* in_sizes, int n_in,
                              void* d_out, int out_size)
{
    (void)in_sizes; (void)n_in; (void)out_size;
    const float* q     = (const float*)d_in[0];
    const float* k     = (const float*)d_in[1];
    const float* v     = (const float*)d_in[2];
    const float* query = (const float*)d_in[3];
    const float* w_qs  = (const float*)d_in[4];
    const float* w_ks  = (const float*)d_in[5];
    const float* w_vs  = (const float*)d_in[6];
    const float* w_qu  = (const float*)d_in[7];
    const float* fc_w  = (const float*)d_in[8];
    const float* fc_b  = (const float*)d_in[9];
    const float* ln_w  = (const float*)d_in[10];
    const float* ln_b  = (const float*)d_in[11];
    float* out = (float*)d_out;

    float *pPQ, *pPK, *pPV, *pPU, *pOUT, *pA, *pQT, *pVF;
    cudaGetSymbolAddress((void**)&pPQ,  g_PQ);
    cudaGetSymbolAddress((void**)&pPK,  g_PK);
    cudaGetSymbolAddress((void**)&pPV,  g_PV);
    cudaGetSymbolAddress((void**)&pPU,  g_PU);
    cudaGetSymbolAddress((void**)&pOUT, g_OUT);
    cudaGetSymbolAddress((void**)&pA,   g_A);
    cudaGetSymbolAddress((void**)&pQT,  g_QT);
    cudaGetSymbolAddress((void**)&pVF,  g_VF);

    cudaFuncSetAttribute(attn_self,  cudaFuncAttributeMaxDynamicSharedMemorySize, 2 * 16384 * 4);
    cudaFuncSetAttribute(attn_query, cudaFuncAttributeMaxDynamicSharedMemorySize,
                         (16384 + 64 * 260 + 512) * 4);

    dim3 thr(256);

    // All four projections in one launch (tf32 tensor path)
    proj4<<<dim3(8, 16, 4), thr>>>(q, k, v, query, w_qs, w_ks, w_vs, w_qu,
                                   pPQ, pPK, pPV, pPU);

    // Self-attention (fused softmax-V)
    attn_self<<<dim3(4, B_, H_), thr, 2 * 16384 * 4>>>(pPQ, pPK, pPV, pOUT);

    // Query attention probs (transposed layout)
    attn_query<<<dim3(B_, H_), thr, (16384 + 64 * 260 + 512) * 4>>>(pPU, pPK, pQT);

    // A = OUT @ fc_w^T  and  VF[h] = PV_h @ fc_w_h^T  in one launch
    gemm_avf<<<dim3(8, 16, 9), thr>>>(pOUT, pPV, fc_w, pA, pVF);

    // Combine + residual + LayerNorm -> output
    combine_ln<<<dim3(LK_, B_), thr>>>(pVF, pA, pQT, q, fc_b, ln_w, ln_b, out);
}